// round 1
// baseline (speedup 1.0000x reference)
#include <cuda_runtime.h>
#include <cstdint>

// Problem constants (fixed by the dataset):
//   x:   [B=32, D=64, T=4096] float32  -> N = B*T = 131072 tokens, x_flat row stride T
//   emb: [K=512, D=64] float32
//   out: quantized flat [N*D] (torch-style .view => gathered [N,D] memory) + loss scalar
#define VQ_B 32
#define VQ_D 64
#define VQ_T 4096
#define VQ_K 512
#define VQ_N (VQ_B * VQ_T)          // 131072
#define TOK_PER_BLK 256
#define NBLOCKS (VQ_N / TOK_PER_BLK) // 512

// Deterministic loss reduction scratch (allocation-free: __device__ global).
__device__ double g_vq_loss_partials[NBLOCKS];

__global__ __launch_bounds__(TOK_PER_BLK)
void vq_main_kernel(const float* __restrict__ x,
                    const float* __restrict__ emb,
                    float* __restrict__ out)
{
    extern __shared__ float smem[];
    float* s_emb = smem;                 // [K][D] row-major, 128 KB
    float* s_se  = smem + VQ_K * VQ_D;   // [K] codeword squared norms, 2 KB
    __shared__ double s_red[TOK_PER_BLK];

    const int tid = threadIdx.x;

    // ---- Stage emb into smem (coalesced float4) ----
    {
        const float4* e4 = reinterpret_cast<const float4*>(emb);
        float4* s4 = reinterpret_cast<float4*>(s_emb);
        #pragma unroll
        for (int i = tid; i < VQ_K * VQ_D / 4; i += TOK_PER_BLK) s4[i] = e4[i];
    }
    __syncthreads();

    // ---- se[k] = fp32 sequential sum of fl(e*e), mimicking jnp.sum(emb*emb, axis=1) ----
    for (int k = tid; k < VQ_K; k += TOK_PER_BLK) {
        float s = 0.0f;
        const float* er = &s_emb[k * VQ_D];
        #pragma unroll
        for (int d = 0; d < VQ_D; d++)
            s = __fadd_rn(s, __fmul_rn(er[d], er[d]));
        s_se[k] = s;
    }
    __syncthreads();

    // ---- Per-thread token ----
    const int n = blockIdx.x * TOK_PER_BLK + tid;   // token index, n = b*T + t
    const int b = n >> 12;                          // n / 4096
    const int t = n & (VQ_T - 1);

    // Load x_flat[n][:] = x[b, d, t] (stride T) into registers. Warp lanes share d,
    // consecutive t -> fully coalesced 128B per d.
    const float* xb = x + (size_t)b * VQ_D * VQ_T + t;
    float xr[VQ_D];
    #pragma unroll
    for (int d = 0; d < VQ_D; d++) xr[d] = xb[(size_t)d * VQ_T];

    // sx = fp32 sequential sum of fl(x*x)  (mimic jnp: multiply then sum, no FMA)
    float sx = 0.0f;
    #pragma unroll
    for (int d = 0; d < VQ_D; d++)
        sx = __fadd_rn(sx, __fmul_rn(xr[d], xr[d]));

    // ---- Argmin over K codewords; 8 accumulator chains per k-chunk ----
    float best = 3.402823466e38f;
    int bestk = 0;

    #pragma unroll 1
    for (int k0 = 0; k0 < VQ_K; k0 += 8) {
        float acc[8];
        #pragma unroll
        for (int kk = 0; kk < 8; kk++) acc[kk] = 0.0f;

        #pragma unroll
        for (int d = 0; d < VQ_D; d += 4) {
            #pragma unroll
            for (int kk = 0; kk < 8; kk++) {
                // broadcast LDS.128 (all lanes same address -> conflict-free)
                float4 ev = *reinterpret_cast<const float4*>(&s_emb[(k0 + kk) * VQ_D + d]);
                // fmaf in ascending-d order: mirrors a sequential fp32 FMA dot product
                acc[kk] = fmaf(xr[d + 0], ev.x, acc[kk]);
                acc[kk] = fmaf(xr[d + 1], ev.y, acc[kk]);
                acc[kk] = fmaf(xr[d + 2], ev.z, acc[kk]);
                acc[kk] = fmaf(xr[d + 3], ev.w, acc[kk]);
            }
        }

        #pragma unroll
        for (int kk = 0; kk < 8; kk++) {
            // dist = fl( fl(sx + se_k) - fl(2*dot_k) ) : exact reference rounding order
            float dist = __fsub_rn(__fadd_rn(sx, s_se[k0 + kk]),
                                   __fmul_rn(2.0f, acc[kk]));
            if (dist < best) { best = dist; bestk = k0 + kk; }  // first-index tie-break
        }
    }

    // ---- Epilogue: gather codeword -> out[n*64 ..], fused loss accumulation ----
    // Loss pairs out (gathered [N,D] memory) with x *flat memory* (the .view trick):
    // x_flat_mem[n*64 + d] is contiguous.
    float* o = out + (size_t)n * VQ_D;
    const float* xf = x + (size_t)n * VQ_D;
    const float* eb = emb + (size_t)bestk * VQ_D;   // global read (L2-resident), avoids
                                                    // 32-way smem bank conflicts on gather
    double lsum = 0.0;
    #pragma unroll
    for (int d = 0; d < VQ_D; d += 4) {
        float4 ev = *reinterpret_cast<const float4*>(&eb[d]);
        float4 xv = *reinterpret_cast<const float4*>(&xf[d]);
        *reinterpret_cast<float4*>(&o[d]) = ev;
        // (q - x)^2 squared in fp32 (mimic ref), accumulated in double for accuracy
        float d0 = __fsub_rn(ev.x, xv.x);
        float d1 = __fsub_rn(ev.y, xv.y);
        float d2 = __fsub_rn(ev.z, xv.z);
        float d3 = __fsub_rn(ev.w, xv.w);
        lsum += (double)__fmul_rn(d0, d0);
        lsum += (double)__fmul_rn(d1, d1);
        lsum += (double)__fmul_rn(d2, d2);
        lsum += (double)__fmul_rn(d3, d3);
    }

    // ---- Deterministic block reduction of loss partials ----
    s_red[tid] = lsum;
    __syncthreads();
    #pragma unroll
    for (int s = TOK_PER_BLK / 2; s > 0; s >>= 1) {
        if (tid < s) s_red[tid] += s_red[tid + s];
        __syncthreads();
    }
    if (tid == 0) g_vq_loss_partials[blockIdx.x] = s_red[0];
}

__global__ void vq_loss_kernel(float* __restrict__ out)
{
    // Single thread: deterministic fixed-order sum of 512 doubles.
    double s = 0.0;
    for (int i = 0; i < NBLOCKS; i++) s += g_vq_loss_partials[i];
    float m = (float)(s / (double)(VQ_N * VQ_D));
    // loss = mean + 0.25*mean, with reference's fp32 rounding of the combine
    out[(size_t)VQ_N * VQ_D] = __fadd_rn(m, __fmul_rn(0.25f, m));
}

extern "C" void kernel_launch(void* const* d_in, const int* in_sizes, int n_in,
                              void* d_out, int out_size)
{
    const float* x   = (const float*)d_in[0];   // [32, 64, 4096]
    const float* emb = (const float*)d_in[1];   // [512, 64]
    float* out = (float*)d_out;

    const int smem_bytes = (VQ_K * VQ_D + VQ_K) * (int)sizeof(float); // 133120
    static bool attr_set = false;
    if (!attr_set) {
        cudaFuncSetAttribute(vq_main_kernel,
                             cudaFuncAttributeMaxDynamicSharedMemorySize, smem_bytes);
        attr_set = true;
    }

    vq_main_kernel<<<NBLOCKS, TOK_PER_BLK, smem_bytes>>>(x, emb, out);

    if (out_size > VQ_N * VQ_D) {
        vq_loss_kernel<<<1, 1>>>(out);
    }
}